// round 13
// baseline (speedup 1.0000x reference)
#include <cuda_runtime.h>
#include <cstdint>

// Local covariance: out = boxmean5( (center(x)-boxmean5(x)) * (center(y)-boxmean5(y)) )
// x,y: [16,1,1024,1024] f32 -> out: [16,1,1016,1016] f32
//
// R13: per-warp cp.async SMEM ring is now the ONLY row storage: current row,
// row-5 (vertical-sum subtract) and row-2 (center) are all read from the ring
// (6 conflict-free LDS.128/row), eliminating the xr/yr register rings
// (~40 regs). 5 blocks/SM, 20 warps/SM, grid 720 = one wave.
// Ring stage of row rrp = (rrp+5)&7; stages for rows r0-5..r0-1 zero-primed.
// Refill distance 2 (stage re-written one full phase after last read).
// No barriers, no __syncthreads.

#define H  1024
#define W  1024
#define OH 1016
#define OW 1016
#define NB 16

#define CPWARP 120            // valid output cols per warp (128 raw - 8 halo)
#define NCS    9              // ceil(1016/120)
#define ORS    52             // output rows per strip
#define IRS    60             // input rows per strip (= ORS + 8, multiple of 5)
#define NRS    20             // 20*52 = 1040 >= 1016
#define DEPTH  8

__device__ __forceinline__ void cp16(uint32_t dst, const void* src, uint32_t zf)
{
    // 16-byte async copy; zf==0 -> zero-fill (no global read)
    asm volatile("cp.async.cg.shared.global [%0], [%1], 16, %2;\n"
                 :: "r"(dst), "l"(src), "r"(zf) : "memory");
}

__global__ __launch_bounds__(128, 5)
void cov_kernel(const float* __restrict__ x,
                const float* __restrict__ y,
                float* __restrict__ out)
{
    // per-warp ring: 8 stages x (32 lanes x 16B x + 32 lanes x 16B y) = 8KB/warp
    __shared__ __align__(16) float4 ring[4][DEPTH][64];

    const int lane = threadIdx.x & 31;
    const int wrp  = threadIdx.x >> 5;

    const int cs = blockIdx.x;               // column strip 0..8
    const int rs = blockIdx.y * 4 + wrp;     // row strip 0..19
    const int b  = blockIdx.z;

    const int c0 = cs * CPWARP + lane * 4;   // first raw col of lane
    const int r0 = rs * ORS;                 // first input row of strip

    const float* __restrict__ xb = x + (long)b * (H * W);
    const float* __restrict__ yb = y + (long)b * (H * W);
    float*       __restrict__ ob = out + (long)b * (OH * OW);

    const bool colok = (c0 < W);
    const int  cc    = colok ? c0 : 0;                 // clamped col (address safety)
    const bool outok = (lane < 30) && (c0 < OW);
    const float inv25 = 1.0f / 25.0f;

    const uint32_t zfc = colok ? 16u : 0u;
    const uint32_t sb  = (uint32_t)__cvta_generic_to_shared(&ring[wrp][0][0]);
    const uint32_t sll = lane * 16;

    // ---- prime: stages 0..6 <- rows r0-5..r0+1 (first 5 zero-filled) ----
    #pragma unroll
    for (int d = 0; d < 7; ++d) {
        const int row = r0 - 5 + d;
        const int rL  = (row >= 0 && row < H) ? row : 0;
        const uint32_t zf = (d >= 5 && row < H) ? zfc : 0u;
        const uint32_t dst = sb + ((uint32_t)d << 10) + sll;
        cp16(dst,       xb + (long)rL * W + cc, zf);
        cp16(dst + 512, yb + (long)rL * W + cc, zf);
        asm volatile("cp.async.commit_group;" ::: "memory");
    }

    // per-lane running state (no raw-row register rings!)
    float hpr[5][4];
    float vsx[4], vsy[4], vhp[4];
    #pragma unroll
    for (int s = 0; s < 5; ++s)
        #pragma unroll
        for (int i = 0; i < 4; ++i) hpr[s][i] = 0.f;
    #pragma unroll
    for (int i = 0; i < 4; ++i) { vsx[i] = 0.f; vsy[i] = 0.f; vhp[i] = 0.f; }

    for (int rr = 0; rr < IRS; rr += 5) {
        #pragma unroll
        for (int ph = 0; ph < 5; ++ph) {
            const int rrp = rr + ph;
            const uint32_t stc = (uint32_t)(rrp + 5) & (DEPTH - 1);  // current row
            const uint32_t sto = (uint32_t)(rrp)     & (DEPTH - 1);  // row rrp-5
            const uint32_t stm = (uint32_t)(rrp + 3) & (DEPTH - 1);  // row rrp-2

            // ---- row rrp ready (only the row-(rrp+1) group may be outstanding) ----
            asm volatile("cp.async.wait_group 1;" ::: "memory");

            float4 xc4 = ring[wrp][stc][lane];        // current row x
            float4 yc4 = ring[wrp][stc][32 + lane];   // current row y
            float4 xo4 = ring[wrp][sto][lane];        // row rrp-5 x
            float4 yo4 = ring[wrp][sto][32 + lane];   // row rrp-5 y
            float4 xm4 = ring[wrp][stm][lane];        // row rrp-2 x (centers)
            float4 ym4 = ring[wrp][stm][32 + lane];   // row rrp-2 y

            // ---- refill stage of row rrp+2 (= stage (rrp+7)&7, last read one phase ago) ----
            {
                const int row = r0 + rrp + 2;
                const int rL  = row < H ? row : (H - 1);
                const uint32_t zf = ((rrp + 2) < IRS && row < H) ? zfc : 0u;
                const uint32_t dst = sb + ((((uint32_t)(rrp + 7)) & (DEPTH - 1)) << 10) + sll;
                cp16(dst,       xb + (long)rL * W + cc, zf);
                cp16(dst + 512, yb + (long)rL * W + cc, zf);
                asm volatile("cp.async.commit_group;" ::: "memory");
            }

            // ---- vertical running 5-sums: += row rrp - row rrp-5 ----
            vsx[0] += xc4.x - xo4.x; vsx[1] += xc4.y - xo4.y;
            vsx[2] += xc4.z - xo4.z; vsx[3] += xc4.w - xo4.w;
            vsy[0] += yc4.x - yo4.x; vsy[1] += yc4.y - yo4.y;
            vsy[2] += yc4.z - yo4.z; vsy[3] += yc4.w - yo4.w;

            // ---- horizontal 5-sums of vertical sums -> 5x5 box sums ----
            float nx[4], ny[4];
            #pragma unroll
            for (int i = 0; i < 4; ++i) {
                nx[i] = __shfl_down_sync(0xffffffffu, vsx[i], 1);
                ny[i] = __shfl_down_sync(0xffffffffu, vsy[i], 1);
            }
            float bx[4], by[4];
            {
                float t = (vsx[0] + vsx[1]) + (vsx[2] + vsx[3]);
                bx[0] = t + nx[0];
                bx[1] = bx[0] - vsx[0] + nx[1];
                bx[2] = bx[1] - vsx[1] + nx[2];
                bx[3] = bx[2] - vsx[2] + nx[3];
                t = (vsy[0] + vsy[1]) + (vsy[2] + vsy[3]);
                by[0] = t + ny[0];
                by[1] = by[0] - vsy[0] + ny[1];
                by[2] = by[1] - vsy[1] + ny[2];
                by[3] = by[2] - vsy[2] + ny[3];
            }

            // ---- center pixels: row rrp-2, cols c0+2..c0+5 ----
            float cx[4], cy[4];
            cx[0] = xm4.z; cx[1] = xm4.w;
            cx[2] = __shfl_down_sync(0xffffffffu, xm4.x, 1);
            cx[3] = __shfl_down_sync(0xffffffffu, xm4.y, 1);
            cy[0] = ym4.z; cy[1] = ym4.w;
            cy[2] = __shfl_down_sync(0xffffffffu, ym4.x, 1);
            cy[3] = __shfl_down_sync(0xffffffffu, ym4.y, 1);

            float pc[4];
            #pragma unroll
            for (int i = 0; i < 4; ++i)
                pc[i] = (cx[i] - bx[i] * inv25) * (cy[i] - by[i] * inv25);

            // ---- horizontal 5-sum of p ----
            float np[4];
            #pragma unroll
            for (int i = 0; i < 4; ++i)
                np[i] = __shfl_down_sync(0xffffffffu, pc[i], 1);

            float hp0, hp1, hp2, hp3;
            {
                float t = (pc[0] + pc[1]) + (pc[2] + pc[3]);
                hp0 = t + np[0];
                hp1 = hp0 - pc[0] + np[1];
                hp2 = hp1 - pc[1] + np[2];
                hp3 = hp2 - pc[2] + np[3];
            }
            if (rrp < 4) { hp0 = 0.f; hp1 = 0.f; hp2 = 0.f; hp3 = 0.f; }

            // ---- vertical running 5-sum of hp -> output row r0+rrp-8 ----
            vhp[0] += hp0 - hpr[ph][0]; hpr[ph][0] = hp0;
            vhp[1] += hp1 - hpr[ph][1]; hpr[ph][1] = hp1;
            vhp[2] += hp2 - hpr[ph][2]; hpr[ph][2] = hp2;
            vhp[3] += hp3 - hpr[ph][3]; hpr[ph][3] = hp3;

            if (rrp >= 8) {
                const int orow = r0 + rrp - 8;
                if (outok && orow < OH) {
                    float4 o = make_float4(vhp[0] * inv25, vhp[1] * inv25,
                                           vhp[2] * inv25, vhp[3] * inv25);
                    __stcs((float4*)(ob + (long)orow * OW + c0), o);
                }
            }
        }
    }
}

extern "C" void kernel_launch(void* const* d_in, const int* in_sizes, int n_in,
                              void* d_out, int out_size)
{
    (void)in_sizes; (void)n_in; (void)out_size;
    const float* x = (const float*)d_in[0];
    const float* y = (const float*)d_in[1];
    float* out = (float*)d_out;

    dim3 grid(NCS, NRS / 4, NB);   // 9 col strips x 20 row strips x 16 images
    cov_kernel<<<grid, 128>>>(x, y, out);
}

// round 14
// speedup vs baseline: 1.1158x; 1.1158x over previous
#include <cuda_runtime.h>
#include <cstdint>

// Local covariance: out = boxmean5( (center(x)-boxmean5(x)) * (center(y)-boxmean5(y)) )
// x,y: [16,1,1024,1024] f32 -> out: [16,1,1016,1016] f32
//
// R14 = R11 structure (register rings + shuffles + per-warp depth-8 cp.async
// SMEM ring, 16 warps/SM) with:
//  - warmup gate removed (early hp values cancel exactly via the ring algebra)
//  - packed f32x2 arithmetic (add/mul/fma.rn.f32x2) for all x/y-paired math.

#define H  1024
#define W  1024
#define OH 1016
#define OW 1016
#define NB 16

#define CPWARP 120            // valid output cols per warp (128 raw - 8 halo)
#define NCS    9              // ceil(1016/120)
#define ORS    67             // output rows per strip
#define IRS    75             // input rows per strip (= ORS + 8, multiple of 5)
#define NRS    16             // 16*67 = 1072 >= 1016
#define DEPTH  8              // cp.async pipeline depth (rows in flight)

typedef unsigned long long u64;

__device__ __forceinline__ u64 pk2(float lo, float hi)
{ u64 r; asm("mov.b64 %0, {%1, %2};" : "=l"(r) : "f"(lo), "f"(hi)); return r; }

__device__ __forceinline__ void upk2(float& lo, float& hi, u64 p)
{ asm("mov.b64 {%0, %1}, %2;" : "=f"(lo), "=f"(hi) : "l"(p)); }

__device__ __forceinline__ u64 addx2(u64 a, u64 b)
{ u64 d; asm("add.rn.f32x2 %0, %1, %2;" : "=l"(d) : "l"(a), "l"(b)); return d; }

__device__ __forceinline__ u64 mulx2(u64 a, u64 b)
{ u64 d; asm("mul.rn.f32x2 %0, %1, %2;" : "=l"(d) : "l"(a), "l"(b)); return d; }

__device__ __forceinline__ u64 fmax2(u64 a, u64 b, u64 c)
{ u64 d; asm("fma.rn.f32x2 %0, %1, %2, %3;" : "=l"(d) : "l"(a), "l"(b), "l"(c)); return d; }

__device__ __forceinline__ void cp16(uint32_t dst, const void* src, uint32_t zf)
{
    // 16-byte async copy; zf==0 -> zero-fill (no global read)
    asm volatile("cp.async.cg.shared.global [%0], [%1], 16, %2;\n"
                 :: "r"(dst), "l"(src), "r"(zf) : "memory");
}

__global__ __launch_bounds__(128, 4)
void cov_kernel(const float* __restrict__ x,
                const float* __restrict__ y,
                float* __restrict__ out)
{
    // per-warp ring: DEPTH stages x (32 lanes x 16B x + 32 lanes x 16B y) = 1KB/stage
    __shared__ __align__(16) float4 ring[4][DEPTH][64];

    const int lane = threadIdx.x & 31;
    const int wrp  = threadIdx.x >> 5;

    const int cs = blockIdx.x;               // column strip 0..8
    const int rs = blockIdx.y * 4 + wrp;     // row strip 0..15
    const int b  = blockIdx.z;

    const int c0 = cs * CPWARP + lane * 4;   // first raw col of lane
    const int r0 = rs * ORS;                 // first input row of strip

    const float* __restrict__ xb = x + (long)b * (H * W);
    const float* __restrict__ yb = y + (long)b * (H * W);
    float*       __restrict__ ob = out + (long)b * (OH * OW);

    const bool colok = (c0 < W);
    const int  cc    = colok ? c0 : 0;                 // clamped col (address safety)
    const bool outok = (lane < 30) && (c0 < OW);
    const float inv25 = 1.0f / 25.0f;

    const uint32_t zfc = colok ? 16u : 0u;
    const uint32_t sb  = (uint32_t)__cvta_generic_to_shared(&ring[wrp][0][0]);
    const uint32_t sll = lane * 16;

    // ---- prime pipeline: rows r0 .. r0+DEPTH-1 into stages 0..DEPTH-1 ----
    #pragma unroll
    for (int d = 0; d < DEPTH; ++d) {
        const int row = r0 + d;
        const int rL  = row < H ? row : (H - 1);
        const uint32_t zf = (row < H) ? zfc : 0u;
        const uint32_t dst = sb + ((uint32_t)d << 10) + sll;
        cp16(dst,       xb + (long)rL * W + cc, zf);
        cp16(dst + 512, yb + (long)rL * W + cc, zf);
        asm volatile("cp.async.commit_group;" ::: "memory");
    }

    // packed state: each u64 = (x-quantity, y-quantity)
    u64 xyr[5][4];      // raw-row ring, (x,y) per col
    u64 vsP[4];         // vertical running 5-sums (vsx, vsy)
    u64 hprP[5][2];     // hp ring: (hp0,hp1),(hp2,hp3)
    u64 vhpP[2];        // vertical running 5-sum of hp
    #pragma unroll
    for (int s = 0; s < 5; ++s) {
        #pragma unroll
        for (int i = 0; i < 4; ++i) xyr[s][i] = 0ull;
        hprP[s][0] = 0ull; hprP[s][1] = 0ull;
    }
    #pragma unroll
    for (int i = 0; i < 4; ++i) vsP[i] = 0ull;
    vhpP[0] = 0ull; vhpP[1] = 0ull;

    const u64 neg1P   = pk2(-1.f, -1.f);
    const u64 ninv25P = pk2(-inv25, -inv25);
    const u64 inv25P  = pk2(inv25, inv25);

    for (int rr = 0; rr < IRS; rr += 5) {
        #pragma unroll
        for (int ph = 0; ph < 5; ++ph) {
            const int rrp = rr + ph;
            const int st  = rrp & (DEPTH - 1);

            // ---- wait for row rrp's copies, consume ----
            asm volatile("cp.async.wait_group 7;" ::: "memory");
            float4 xv = ring[wrp][st][lane];
            float4 yv = ring[wrp][st][32 + lane];

            // ---- refill same stage with row rrp+DEPTH ----
            {
                const int row = r0 + rrp + DEPTH;
                const int rL  = row < H ? row : (H - 1);
                const uint32_t zf = ((rrp + DEPTH) < IRS && row < H) ? zfc : 0u;
                const uint32_t dst = sb + ((uint32_t)st << 10) + sll;
                cp16(dst,       xb + (long)rL * W + cc, zf);
                cp16(dst + 512, yb + (long)rL * W + cc, zf);
                asm volatile("cp.async.commit_group;" ::: "memory");
            }

            // ---- pack new row, vertical running 5-sums (packed) ----
            u64 xyn[4];
            xyn[0] = pk2(xv.x, yv.x); xyn[1] = pk2(xv.y, yv.y);
            xyn[2] = pk2(xv.z, yv.z); xyn[3] = pk2(xv.w, yv.w);
            #pragma unroll
            for (int i = 0; i < 4; ++i) {
                vsP[i] = addx2(vsP[i], fmax2(xyr[ph][i], neg1P, xyn[i]));
                xyr[ph][i] = xyn[i];
            }

            // ---- neighbor (lane+1) vertical sums via half-shuffles ----
            u64 nP[4];
            #pragma unroll
            for (int i = 0; i < 4; ++i) {
                float lo, hi;
                upk2(lo, hi, vsP[i]);
                nP[i] = pk2(__shfl_down_sync(0xffffffffu, lo, 1),
                            __shfl_down_sync(0xffffffffu, hi, 1));
            }

            // ---- horizontal 5-sums -> 5x5 box sums (packed sliding chain) ----
            u64 bP[4];
            {
                u64 t = addx2(addx2(vsP[0], vsP[1]), addx2(vsP[2], vsP[3]));
                bP[0] = addx2(t, nP[0]);
                bP[1] = addx2(fmax2(vsP[0], neg1P, bP[0]), nP[1]);
                bP[2] = addx2(fmax2(vsP[1], neg1P, bP[1]), nP[2]);
                bP[3] = addx2(fmax2(vsP[2], neg1P, bP[2]), nP[3]);
            }

            // ---- center pixels: row rrp-2 (ring slot (ph+3)%5), col u+2 ----
            const int sc = (ph + 3) % 5;
            u64 cP[4];
            cP[0] = xyr[sc][2];
            cP[1] = xyr[sc][3];
            {
                float l0, h0, l1, h1;
                upk2(l0, h0, xyr[sc][0]);
                upk2(l1, h1, xyr[sc][1]);
                cP[2] = pk2(__shfl_down_sync(0xffffffffu, l0, 1),
                            __shfl_down_sync(0xffffffffu, h0, 1));
                cP[3] = pk2(__shfl_down_sync(0xffffffffu, l1, 1),
                            __shfl_down_sync(0xffffffffu, h1, 1));
            }

            // ---- pc = (cx - bx/25) * (cy - by/25) ----
            float pc[4];
            #pragma unroll
            for (int i = 0; i < 4; ++i) {
                u64 t = fmax2(bP[i], ninv25P, cP[i]);
                float lo, hi;
                upk2(lo, hi, t);
                pc[i] = lo * hi;
            }

            // ---- horizontal 5-sum of p (scalar chain; NO warmup gate:
            //      early garbage values cancel exactly via the hp ring) ----
            float np[4];
            #pragma unroll
            for (int i = 0; i < 4; ++i)
                np[i] = __shfl_down_sync(0xffffffffu, pc[i], 1);

            float hp0, hp1, hp2, hp3;
            {
                float t = (pc[0] + pc[1]) + (pc[2] + pc[3]);
                hp0 = t + np[0];
                hp1 = hp0 - pc[0] + np[1];
                hp2 = hp1 - pc[1] + np[2];
                hp3 = hp2 - pc[2] + np[3];
            }

            // ---- vertical running 5-sum of hp (packed) ----
            u64 hp01 = pk2(hp0, hp1);
            u64 hp23 = pk2(hp2, hp3);
            vhpP[0] = addx2(vhpP[0], fmax2(hprP[ph][0], neg1P, hp01)); hprP[ph][0] = hp01;
            vhpP[1] = addx2(vhpP[1], fmax2(hprP[ph][1], neg1P, hp23)); hprP[ph][1] = hp23;

            if (rrp >= 8) {
                const int orow = r0 + rrp - 8;
                if (outok && orow < OH) {
                    u64 o01 = mulx2(vhpP[0], inv25P);
                    u64 o23 = mulx2(vhpP[1], inv25P);
                    float o0, o1, o2, o3;
                    upk2(o0, o1, o01);
                    upk2(o2, o3, o23);
                    __stcs((float4*)(ob + (long)orow * OW + c0),
                           make_float4(o0, o1, o2, o3));
                }
            }
        }
    }
}

extern "C" void kernel_launch(void* const* d_in, const int* in_sizes, int n_in,
                              void* d_out, int out_size)
{
    (void)in_sizes; (void)n_in; (void)out_size;
    const float* x = (const float*)d_in[0];
    const float* y = (const float*)d_in[1];
    float* out = (float*)d_out;

    dim3 grid(NCS, NRS / 4, NB);   // 9 col strips x 16 row strips x 16 images
    cov_kernel<<<grid, 128>>>(x, y, out);
}